// round 6
// baseline (speedup 1.0000x reference)
#include <cuda_runtime.h>

#define HH 256
#define WW 256
#define BATCH 8
#define HW 65536

typedef unsigned long long ull;

// Scratch (allocation-free rule: __device__ globals)
__device__ float g_x[BATCH * 16 * HW];          // in_conv output  (33.5 MB)
__device__ float g_xs[4 * BATCH * 16 * HW];     // dwconv outputs  (134 MB)

// ---------------- packed f32x2 helpers (sm_100+) ----------------
__device__ __forceinline__ ull pk2(float lo, float hi) {
    ull r;
    asm("mov.b64 %0, {%1, %2};" : "=l"(r) : "r"(__float_as_uint(lo)), "r"(__float_as_uint(hi)));
    return r;
}
__device__ __forceinline__ void upk2(ull v, float& lo, float& hi) {
    unsigned a, b;
    asm("mov.b64 {%0, %1}, %2;" : "=r"(a), "=r"(b) : "l"(v));
    lo = __uint_as_float(a); hi = __uint_as_float(b);
}
__device__ __forceinline__ ull fma2(ull a, ull b, ull c) {
    ull d; asm("fma.rn.f32x2 %0, %1, %2, %3;" : "=l"(d) : "l"(a), "l"(b), "l"(c)); return d;
}
__device__ __forceinline__ ull add2(ull a, ull b) {
    ull d; asm("add.rn.f32x2 %0, %1, %2;" : "=l"(d) : "l"(a), "l"(b)); return d;
}
__device__ __forceinline__ ull mul2(ull a, ull b) {
    ull d; asm("mul.rn.f32x2 %0, %1, %2;" : "=l"(d) : "l"(a), "l"(b)); return d;
}

// ---------------------------------------------------------------------------
// K1: 1x1 in_conv 64 -> 16, packed f32x2 FFMA2 (2 px / thread)
// ---------------------------------------------------------------------------
__global__ __launch_bounds__(256, 3) void k_inconv(const ull* __restrict__ cen2,
                                                   const float* __restrict__ w,
                                                   const float* __restrict__ bias) {
    __shared__ ull sw[1024];     // {w,w} packed
    __shared__ ull sb[16];
    for (int i = threadIdx.x; i < 1024; i += 256) { float v = w[i]; sw[i] = pk2(v, v); }
    if (threadIdx.x < 16) { float v = bias[threadIdx.x]; sb[threadIdx.x] = pk2(v, v); }
    __syncthreads();

    int idx = blockIdx.x * 256 + threadIdx.x;   // 0 .. 262143  (b, p2)
    int b = idx >> 15;
    int p2 = idx & 32767;
    const ull* cp = cen2 + (size_t)(b * 64) * 32768 + p2;

    ull acc[16];
#pragma unroll
    for (int o = 0; o < 16; o++) acc[o] = sb[o];

#pragma unroll 8
    for (int i = 0; i < 64; i++) {
        ull v = __ldg(cp + (size_t)i * 32768);
#pragma unroll
        for (int o = 0; o < 16; o++) acc[o] = fma2(v, sw[o * 64 + i], acc[o]);
    }
    ull* xp = reinterpret_cast<ull*>(g_x) + (size_t)(b * 16) * 32768 + p2;
#pragma unroll
    for (int o = 0; o < 16; o++) xp[(size_t)o * 32768] = acc[o];
}

// ---------------------------------------------------------------------------
// K2: all 4 depthwise convs (s = 1,3,5,7), tile 32x16, 2 px per thread,
//     register-prefetch pipeline over channels.  (unchanged from R4)
// ---------------------------------------------------------------------------
template <int S>
__device__ __forceinline__ void dw2(const float* __restrict__ sx, int ty, int c0,
                                    const float* __restrict__ wk, float bias,
                                    float& o0, float& o1) {
    constexpr int P = S / 2;
    float a0 = bias, a1 = bias;
#pragma unroll
    for (int kh = 0; kh < S; kh++) {
        const float* row = sx + (ty + 3 - P + kh) * 39 + (c0 + 3 - P);
        float v[S + 1];
#pragma unroll
        for (int j = 0; j <= S; j++) v[j] = row[j];
#pragma unroll
        for (int kw = 0; kw < S; kw++) {
            float wv = wk[kh * S + kw];
            a0 = fmaf(wv, v[kw], a0);
            a1 = fmaf(wv, v[kw + 1], a1);
        }
    }
    o0 = a0; o1 = a1;
}

__device__ __forceinline__ void dw_prefetch(float r[4], const float* __restrict__ src,
                                            int y0, int x0, int tid) {
#pragma unroll
    for (int j = 0; j < 4; j++) {
        int i = tid + j * 256;
        float v = 0.f;
        if (i < 836) {
            int rr = i / 38, cl = i % 38;
            int gy = y0 - 3 + rr, gx = x0 - 3 + cl;
            if ((unsigned)gy < 256u && (unsigned)gx < 256u)
                v = __ldg(src + gy * 256 + gx);
        }
        r[j] = v;
    }
}

__device__ __forceinline__ void dw_commit(const float r[4], float* __restrict__ sxt,
                                          int tid) {
#pragma unroll
    for (int j = 0; j < 4; j++) {
        int i = tid + j * 256;
        if (i < 836) sxt[(i / 38) * 39 + (i % 38)] = r[j];
    }
}

__global__ __launch_bounds__(256) void k_dw(
    const float* __restrict__ w1, const float* __restrict__ b1,
    const float* __restrict__ w3, const float* __restrict__ b3,
    const float* __restrict__ w5, const float* __restrict__ b5,
    const float* __restrict__ w7, const float* __restrict__ b7) {
    __shared__ float sdw[16 * 84];
    __shared__ float sdb[64];
    __shared__ float sxt[22 * 39];

    int tid = threadIdx.x;
    for (int i = tid; i < 16;  i += 256) sdw[i * 84] = w1[i];
    for (int i = tid; i < 144; i += 256) sdw[(i / 9)  * 84 + 1  + (i % 9)]  = w3[i];
    for (int i = tid; i < 400; i += 256) sdw[(i / 25) * 84 + 10 + (i % 25)] = w5[i];
    for (int i = tid; i < 784; i += 256) sdw[(i / 49) * 84 + 35 + (i % 49)] = w7[i];
    if (tid < 16) {
        sdb[tid * 4 + 0] = b1[tid]; sdb[tid * 4 + 1] = b3[tid];
        sdb[tid * 4 + 2] = b5[tid]; sdb[tid * 4 + 3] = b7[tid];
    }

    int ty = tid >> 4;
    int c0 = (tid & 15) * 2;
    int y0 = blockIdx.y * 16, x0 = blockIdx.x * 32;
    int b = blockIdx.z;
    int h = y0 + ty, wc0 = x0 + c0;

    float rb[4];
    dw_prefetch(rb, g_x + (size_t)(b * 16 + 0) * HW, y0, x0, tid);

#pragma unroll 1
    for (int c = 0; c < 16; c++) {
        __syncthreads();
        dw_commit(rb, sxt, tid);
        __syncthreads();
        if (c < 15)
            dw_prefetch(rb, g_x + (size_t)(b * 16 + c + 1) * HW, y0, x0, tid);

        const float* wcp = sdw + c * 84;
        size_t pix = (size_t)h * 256 + wc0;
        float o0, o1;
        dw2<1>(sxt, ty, c0, wcp + 0,  sdb[c * 4 + 0], o0, o1);
        *reinterpret_cast<float2*>(g_xs + (size_t)((0 * BATCH + b) * 16 + c) * HW + pix) = make_float2(o0, o1);
        dw2<3>(sxt, ty, c0, wcp + 1,  sdb[c * 4 + 1], o0, o1);
        *reinterpret_cast<float2*>(g_xs + (size_t)((1 * BATCH + b) * 16 + c) * HW + pix) = make_float2(o0, o1);
        dw2<5>(sxt, ty, c0, wcp + 10, sdb[c * 4 + 2], o0, o1);
        *reinterpret_cast<float2*>(g_xs + (size_t)((2 * BATCH + b) * 16 + c) * HW + pix) = make_float2(o0, o1);
        dw2<7>(sxt, ty, c0, wcp + 35, sdb[c * 4 + 3], o0, o1);
        *reinterpret_cast<float2*>(g_xs + (size_t)((3 * BATCH + b) * 16 + c) * HW + pix) = make_float2(o0, o1);
    }
}

// ---------------------------------------------------------------------------
// K3: fused tail, tile 32x32, 512 threads, 2 px/thread, packed f32x2 math.
// ---------------------------------------------------------------------------
__device__ __forceinline__ void ce(float& a, float& b) {
    float lo = fminf(a, b);
    float hi = fmaxf(a, b);
    a = lo; b = hi;
}

__device__ __forceinline__ void sort8(float v[8]) {
    ce(v[0], v[1]); ce(v[2], v[3]); ce(v[0], v[2]); ce(v[1], v[3]); ce(v[1], v[2]);
    ce(v[4], v[5]); ce(v[6], v[7]); ce(v[4], v[6]); ce(v[5], v[7]); ce(v[5], v[6]);
    ce(v[0], v[4]); ce(v[1], v[5]); ce(v[2], v[6]); ce(v[3], v[7]);
    ce(v[2], v[4]); ce(v[3], v[5]);
    ce(v[1], v[2]); ce(v[3], v[4]); ce(v[5], v[6]);
}

// Packed branch value for an x-pair. wp: 5 packed weights {w10,w11,w12,2*w13,b1};
// wB scalar block (l2 weights at [5..12], l2 bias at [13]).
template <int S, int C>
__device__ __forceinline__ void branch_val2(const float* __restrict__ sx, int ty,
                                            int tx2, const ull* __restrict__ wp,
                                            const float* __restrict__ wB,
                                            float& ra, float& rb) {
    const float* ctr = sx + (ty + S) * C + (2 * tx2 + S);
    const ull NEG1 = pk2(-1.f, -1.f);
    ull xc = pk2(ctr[0], ctr[1]);
    ull T[8];
    {
        const int offs[8] = {-S * C - S, -S * C, -S * C + S, S,
                             S * C + S, S * C, S * C - S, -S};
#pragma unroll
        for (int j = 0; j < 8; j++) {
            ull n = pk2(ctr[offs[j]], ctr[offs[j] + 1]);
            T[j] = fma2(n, NEG1, xc);       // xc - n
        }
    }
    ull Sv[4];
#pragma unroll
    for (int k = 0; k < 4; k++) Sv[k] = add2(T[k], T[k + 4]);

    ull base[4];
#pragma unroll
    for (int j = 0; j < 4; j++) {
        ull o = fma2(wp[0], Sv[(j + 1) & 3], wp[4]);
        o = fma2(wp[1], Sv[(j + 3) & 3], o);
        base[j] = fma2(wp[2], Sv[(j + 2) & 3], o);
    }
    float va[8], vb[8];
#pragma unroll
    for (int k = 0; k < 8; k++) {
        ull v = mul2(fma2(wp[3], T[(k + 4) & 7], base[k & 3]), T[k]);
        upk2(v, va[k], vb[k]);
    }
    sort8(va);
    sort8(vb);
    float aa = wB[13], bb = wB[13];
#pragma unroll
    for (int j = 0; j < 8; j++) {
        float w2 = wB[5 + j];
        aa = fmaf(va[j], w2, aa);
        bb = fmaf(vb[j], w2, bb);
    }
    ra = aa; rb = bb;
}

template <int S, int NR>
__device__ __forceinline__ void m_prefetch(float r[NR], const float* __restrict__ src,
                                           int y0, int x0, int tid) {
    constexpr int R = 32 + 2 * S, C = 32 + 2 * S;
#pragma unroll
    for (int j = 0; j < NR; j++) {
        int i = tid + j * 512;
        float v = 0.f;
        if (i < R * C) {
            int rr = i / C, cl = i % C;
            int gy = y0 - S + rr, gx = x0 - S + cl;
            if ((unsigned)gy < 256u && (unsigned)gx < 256u)
                v = __ldg(src + gy * 256 + gx);
        }
        r[j] = v;
    }
}

template <int S, int NR>
__device__ __forceinline__ void m_commit(const float r[NR], float* __restrict__ dst,
                                         int tid) {
    constexpr int R = 32 + 2 * S, C = 32 + 2 * S;
#pragma unroll
    for (int j = 0; j < NR; j++) {
        int i = tid + j * 512;
        if (i < R * C) dst[i] = r[j];
    }
}

__global__ __launch_bounds__(512) void k_main(
    const float* __restrict__ l1_w, const float* __restrict__ l1_b,
    const float* __restrict__ l2_w, const float* __restrict__ l2_b,
    const float* __restrict__ base_w, const float* __restrict__ bn_scale,
    const float* __restrict__ bn_bias, const float* __restrict__ final_w,
    const float* __restrict__ final_b, float* __restrict__ out) {
    // Regions for 32x32 tile: S=1: 34x34=1156 @0; S=3: 38x38=1444 @1156;
    // S=5: 42x42=1764 @2600; S=7: 46x46=2116 @4364; total 6480 (25.9 KB)
    __shared__ float sxt[6480];
    __shared__ float swB[4 * 16 * 14];   // per branch/channel: w1[4],b1,w2[8],b2
    __shared__ float sbase[64];
    __shared__ float sbnS[16], sbnB[16], sfw[16];

    int tid = threadIdx.x;
    for (int i = tid; i < 896; i += 512) {
        int e = i % 14;
        int rest = i / 14;
        int cc = rest % 16, br = rest / 16;
        float v;
        if (e < 4) { v = l1_w[(br * 16 + cc) * 4 + e]; if (e == 3) v *= 2.f; }
        else if (e == 4) v = l1_b[br * 16 + cc];
        else if (e < 13) v = l2_w[(br * 16 + cc) * 8 + (e - 5)];
        else v = l2_b[br * 16 + cc];
        swB[i] = v;
    }
    if (tid < 64) sbase[tid] = base_w[tid];
    if (tid < 16) { sbnS[tid] = bn_scale[tid]; sbnB[tid] = bn_bias[tid]; sfw[tid] = final_w[tid]; }

    int tx2 = tid & 15, ty = tid >> 4;    // x-pair 0..15, row 0..31
    int x0 = blockIdx.x * 32, y0 = blockIdx.y * 32;
    int b = blockIdx.z;
    float fb = __ldg(final_b);
    float acc0 = fb, acc1 = fb;

    const float* s1 = g_xs + (size_t)((0 * BATCH + b) * 16) * HW;
    const float* s3 = g_xs + (size_t)((1 * BATCH + b) * 16) * HW;
    const float* s5 = g_xs + (size_t)((2 * BATCH + b) * 16) * HW;
    const float* s7 = g_xs + (size_t)((3 * BATCH + b) * 16) * HW;

    float r1[3], r3[3], r5[4], r7[5];
    m_prefetch<1, 3>(r1, s1, y0, x0, tid);
    m_prefetch<3, 3>(r3, s3, y0, x0, tid);
    m_prefetch<5, 4>(r5, s5, y0, x0, tid);
    m_prefetch<7, 5>(r7, s7, y0, x0, tid);

#pragma unroll 1
    for (int c = 0; c < 16; c++) {
        __syncthreads();
        m_commit<1, 3>(r1, sxt + 0,    tid);
        m_commit<3, 3>(r3, sxt + 1156, tid);
        m_commit<5, 4>(r5, sxt + 2600, tid);
        m_commit<7, 5>(r7, sxt + 4364, tid);
        __syncthreads();
        if (c < 15) {
            size_t off = (size_t)(c + 1) * HW;
            m_prefetch<1, 3>(r1, s1 + off, y0, x0, tid);
            m_prefetch<3, 3>(r3, s3 + off, y0, x0, tid);
            m_prefetch<5, 4>(r5, s5 + off, y0, x0, tid);
            m_prefetch<7, 5>(r7, s7 + off, y0, x0, tid);
        }

        float bva[4], bvb[4];
        {
            const float* wB0 = swB + (0 * 16 + c) * 14;
            ull wp[5]; for (int j = 0; j < 4; j++) wp[j] = pk2(wB0[j], wB0[j]);
            wp[4] = pk2(wB0[4], wB0[4]);
            branch_val2<1, 34>(sxt + 0, ty, tx2, wp, wB0, bva[0], bvb[0]);
        }
        {
            const float* wB1 = swB + (1 * 16 + c) * 14;
            ull wp[5]; for (int j = 0; j < 4; j++) wp[j] = pk2(wB1[j], wB1[j]);
            wp[4] = pk2(wB1[4], wB1[4]);
            branch_val2<3, 38>(sxt + 1156, ty, tx2, wp, wB1, bva[1], bvb[1]);
        }
        {
            const float* wB2 = swB + (2 * 16 + c) * 14;
            ull wp[5]; for (int j = 0; j < 4; j++) wp[j] = pk2(wB2[j], wB2[j]);
            wp[4] = pk2(wB2[4], wB2[4]);
            branch_val2<5, 42>(sxt + 2600, ty, tx2, wp, wB2, bva[2], bvb[2]);
        }
        {
            const float* wB3 = swB + (3 * 16 + c) * 14;
            ull wp[5]; for (int j = 0; j < 4; j++) wp[j] = pk2(wB3[j], wB3[j]);
            wp[4] = pk2(wB3[4], wB3[4]);
            branch_val2<7, 46>(sxt + 4364, ty, tx2, wp, wB3, bva[3], bvb[3]);
        }

        // sort4 ascending per px
        ce(bva[0], bva[1]); ce(bva[2], bva[3]); ce(bva[0], bva[2]); ce(bva[1], bva[3]); ce(bva[1], bva[2]);
        ce(bvb[0], bvb[1]); ce(bvb[2], bvb[3]); ce(bvb[0], bvb[2]); ce(bvb[1], bvb[3]); ce(bvb[1], bvb[2]);

        float y0v = bva[0] * sbase[c * 4 + 0];
        y0v = fmaf(bva[1], sbase[c * 4 + 1], y0v);
        y0v = fmaf(bva[2], sbase[c * 4 + 2], y0v);
        y0v = fmaf(bva[3], sbase[c * 4 + 3], y0v);
        float y1v = bvb[0] * sbase[c * 4 + 0];
        y1v = fmaf(bvb[1], sbase[c * 4 + 1], y1v);
        y1v = fmaf(bvb[2], sbase[c * 4 + 2], y1v);
        y1v = fmaf(bvb[3], sbase[c * 4 + 3], y1v);
        float t0 = fmaf(y0v, sbnS[c], sbnB[c]);
        float t1 = fmaf(y1v, sbnS[c], sbnB[c]);
        float si0 = __fdividef(t0, 1.f + __expf(-t0));
        float si1 = __fdividef(t1, 1.f + __expf(-t1));
        acc0 = fmaf(si0, sfw[c], acc0);
        acc1 = fmaf(si1, sfw[c], acc1);
    }
    float2 o = make_float2(__fdividef(1.f, 1.f + __expf(-acc0)),
                           __fdividef(1.f, 1.f + __expf(-acc1)));
    *reinterpret_cast<float2*>(out + (size_t)b * HW + (size_t)(y0 + ty) * 256 +
                               (x0 + 2 * tx2)) = o;
}

// ---------------------------------------------------------------------------
extern "C" void kernel_launch(void* const* d_in, const int* in_sizes, int n_in,
                              void* d_out, int out_size) {
    (void)in_sizes; (void)n_in; (void)out_size;
    const ull* cen = (const ull*)d_in[0];
    // d_in[1] = mas (unused by the reference computation)
    const float* in_w = (const float*)d_in[2];
    const float* in_b = (const float*)d_in[3];

    k_inconv<<<1024, 256>>>(cen, in_w, in_b);

    dim3 g2(8, 16, 8);   // W/32, H/16, B
    k_dw<<<g2, 256>>>((const float*)d_in[4],  (const float*)d_in[5],
                      (const float*)d_in[6],  (const float*)d_in[7],
                      (const float*)d_in[8],  (const float*)d_in[9],
                      (const float*)d_in[10], (const float*)d_in[11]);

    dim3 g3(8, 8, 8);    // W/32, H/32, B
    k_main<<<g3, 512>>>((const float*)d_in[12], (const float*)d_in[13],
                        (const float*)d_in[14], (const float*)d_in[15],
                        (const float*)d_in[16], (const float*)d_in[17],
                        (const float*)d_in[18], (const float*)d_in[19],
                        (const float*)d_in[20], (float*)d_out);
}

// round 7
// speedup vs baseline: 1.1340x; 1.1340x over previous
#include <cuda_runtime.h>

#define HH 256
#define WW 256
#define BATCH 8
#define HW 65536

typedef unsigned long long ull;

// Scratch (allocation-free rule: __device__ globals)
__device__ float g_x[BATCH * 16 * HW];          // in_conv output  (33.5 MB)
__device__ float g_xs[4 * BATCH * 16 * HW];     // dwconv outputs  (134 MB)

// ---------------- packed f32x2 helpers (sm_100+) ----------------
__device__ __forceinline__ ull pk2(float lo, float hi) {
    ull r;
    asm("mov.b64 %0, {%1, %2};" : "=l"(r) : "r"(__float_as_uint(lo)), "r"(__float_as_uint(hi)));
    return r;
}
__device__ __forceinline__ ull fma2(ull a, ull b, ull c) {
    ull d; asm("fma.rn.f32x2 %0, %1, %2, %3;" : "=l"(d) : "l"(a), "l"(b), "l"(c)); return d;
}

// ---------------------------------------------------------------------------
// K1: 1x1 in_conv 64 -> 16, packed f32x2 FFMA2 (2 px / thread)
// ---------------------------------------------------------------------------
__global__ __launch_bounds__(256, 3) void k_inconv(const ull* __restrict__ cen2,
                                                   const float* __restrict__ w,
                                                   const float* __restrict__ bias) {
    __shared__ ull sw[1024];     // {w,w} packed
    __shared__ ull sb[16];
    for (int i = threadIdx.x; i < 1024; i += 256) { float v = w[i]; sw[i] = pk2(v, v); }
    if (threadIdx.x < 16) { float v = bias[threadIdx.x]; sb[threadIdx.x] = pk2(v, v); }
    __syncthreads();

    int idx = blockIdx.x * 256 + threadIdx.x;   // 0 .. 262143  (b, p2)
    int b = idx >> 15;
    int p2 = idx & 32767;
    const ull* cp = cen2 + (size_t)(b * 64) * 32768 + p2;

    ull acc[16];
#pragma unroll
    for (int o = 0; o < 16; o++) acc[o] = sb[o];

#pragma unroll 8
    for (int i = 0; i < 64; i++) {
        ull v = __ldg(cp + (size_t)i * 32768);
#pragma unroll
        for (int o = 0; o < 16; o++) acc[o] = fma2(v, sw[o * 64 + i], acc[o]);
    }
    ull* xp = reinterpret_cast<ull*>(g_x) + (size_t)(b * 16) * 32768 + p2;
#pragma unroll
    for (int o = 0; o < 16; o++) xp[(size_t)o * 32768] = acc[o];
}

// ---------------------------------------------------------------------------
// K2: all 4 depthwise convs (s = 1,3,5,7), tile 32x16, 2 px per thread,
//     register-prefetch pipeline over channels.
// ---------------------------------------------------------------------------
template <int S>
__device__ __forceinline__ void dw2(const float* __restrict__ sx, int ty, int c0,
                                    const float* __restrict__ wk, float bias,
                                    float& o0, float& o1) {
    constexpr int P = S / 2;
    float a0 = bias, a1 = bias;
#pragma unroll
    for (int kh = 0; kh < S; kh++) {
        const float* row = sx + (ty + 3 - P + kh) * 39 + (c0 + 3 - P);
        float v[S + 1];
#pragma unroll
        for (int j = 0; j <= S; j++) v[j] = row[j];
#pragma unroll
        for (int kw = 0; kw < S; kw++) {
            float wv = wk[kh * S + kw];
            a0 = fmaf(wv, v[kw], a0);
            a1 = fmaf(wv, v[kw + 1], a1);
        }
    }
    o0 = a0; o1 = a1;
}

__device__ __forceinline__ void dw_prefetch(float r[4], const float* __restrict__ src,
                                            int y0, int x0, int tid) {
#pragma unroll
    for (int j = 0; j < 4; j++) {
        int i = tid + j * 256;
        float v = 0.f;
        if (i < 836) {
            int rr = i / 38, cl = i % 38;
            int gy = y0 - 3 + rr, gx = x0 - 3 + cl;
            if ((unsigned)gy < 256u && (unsigned)gx < 256u)
                v = __ldg(src + gy * 256 + gx);
        }
        r[j] = v;
    }
}

__device__ __forceinline__ void dw_commit(const float r[4], float* __restrict__ sxt,
                                          int tid) {
#pragma unroll
    for (int j = 0; j < 4; j++) {
        int i = tid + j * 256;
        if (i < 836) sxt[(i / 38) * 39 + (i % 38)] = r[j];
    }
}

__global__ __launch_bounds__(256) void k_dw(
    const float* __restrict__ w1, const float* __restrict__ b1,
    const float* __restrict__ w3, const float* __restrict__ b3,
    const float* __restrict__ w5, const float* __restrict__ b5,
    const float* __restrict__ w7, const float* __restrict__ b7) {
    __shared__ float sdw[16 * 84];
    __shared__ float sdb[64];
    __shared__ float sxt[22 * 39];

    int tid = threadIdx.x;
    for (int i = tid; i < 16;  i += 256) sdw[i * 84] = w1[i];
    for (int i = tid; i < 144; i += 256) sdw[(i / 9)  * 84 + 1  + (i % 9)]  = w3[i];
    for (int i = tid; i < 400; i += 256) sdw[(i / 25) * 84 + 10 + (i % 25)] = w5[i];
    for (int i = tid; i < 784; i += 256) sdw[(i / 49) * 84 + 35 + (i % 49)] = w7[i];
    if (tid < 16) {
        sdb[tid * 4 + 0] = b1[tid]; sdb[tid * 4 + 1] = b3[tid];
        sdb[tid * 4 + 2] = b5[tid]; sdb[tid * 4 + 3] = b7[tid];
    }

    int ty = tid >> 4;
    int c0 = (tid & 15) * 2;
    int y0 = blockIdx.y * 16, x0 = blockIdx.x * 32;
    int b = blockIdx.z;
    int h = y0 + ty, wc0 = x0 + c0;

    float rb[4];
    dw_prefetch(rb, g_x + (size_t)(b * 16 + 0) * HW, y0, x0, tid);

#pragma unroll 1
    for (int c = 0; c < 16; c++) {
        __syncthreads();
        dw_commit(rb, sxt, tid);
        __syncthreads();
        if (c < 15)
            dw_prefetch(rb, g_x + (size_t)(b * 16 + c + 1) * HW, y0, x0, tid);

        const float* wcp = sdw + c * 84;
        size_t pix = (size_t)h * 256 + wc0;
        float o0, o1;
        dw2<1>(sxt, ty, c0, wcp + 0,  sdb[c * 4 + 0], o0, o1);
        *reinterpret_cast<float2*>(g_xs + (size_t)((0 * BATCH + b) * 16 + c) * HW + pix) = make_float2(o0, o1);
        dw2<3>(sxt, ty, c0, wcp + 1,  sdb[c * 4 + 1], o0, o1);
        *reinterpret_cast<float2*>(g_xs + (size_t)((1 * BATCH + b) * 16 + c) * HW + pix) = make_float2(o0, o1);
        dw2<5>(sxt, ty, c0, wcp + 10, sdb[c * 4 + 2], o0, o1);
        *reinterpret_cast<float2*>(g_xs + (size_t)((2 * BATCH + b) * 16 + c) * HW + pix) = make_float2(o0, o1);
        dw2<7>(sxt, ty, c0, wcp + 35, sdb[c * 4 + 3], o0, o1);
        *reinterpret_cast<float2*>(g_xs + (size_t)((3 * BATCH + b) * 16 + c) * HW + pix) = make_float2(o0, o1);
    }
}

// ---------------------------------------------------------------------------
// K3: fused tail, tile 32x16, 512 threads, scalar math, channel prefetch.
// ---------------------------------------------------------------------------
__device__ __forceinline__ void ce(float& a, float& b) {
    float lo = fminf(a, b);
    float hi = fmaxf(a, b);
    a = lo; b = hi;
}

template <int S, int C>
__device__ __forceinline__ float branch_val(const float* __restrict__ sx, int ty,
                                            int tx, const float* __restrict__ wB) {
    const float* ctr = sx + (ty + S) * C + (tx + S);
    float xc = ctr[0];
    float T[8];
    T[0] = xc - ctr[-S * C - S];
    T[1] = xc - ctr[-S * C];
    T[2] = xc - ctr[-S * C + S];
    T[3] = xc - ctr[S];
    T[4] = xc - ctr[S * C + S];
    T[5] = xc - ctr[S * C];
    T[6] = xc - ctr[S * C - S];
    T[7] = xc - ctr[-S];
    float Sv[4];
#pragma unroll
    for (int k = 0; k < 4; k++) Sv[k] = T[k] + T[k + 4];

    float w10 = wB[0], w11 = wB[1], w12 = wB[2], w13x2 = wB[3], b1 = wB[4];
    float base[4];
#pragma unroll
    for (int j = 0; j < 4; j++) {
        float o = fmaf(w10, Sv[(j + 1) & 3], b1);
        o = fmaf(w11, Sv[(j + 3) & 3], o);
        base[j] = fmaf(w12, Sv[(j + 2) & 3], o);
    }
    float v[8];
#pragma unroll
    for (int k = 0; k < 8; k++)
        v[k] = fmaf(w13x2, T[(k + 4) & 7], base[k & 3]) * T[k];  // wB[3] pre-doubled

    // Batcher odd-even mergesort, 8 elems, 19 CEs, ascending
    ce(v[0], v[1]); ce(v[2], v[3]); ce(v[0], v[2]); ce(v[1], v[3]); ce(v[1], v[2]);
    ce(v[4], v[5]); ce(v[6], v[7]); ce(v[4], v[6]); ce(v[5], v[7]); ce(v[5], v[6]);
    ce(v[0], v[4]); ce(v[1], v[5]); ce(v[2], v[6]); ce(v[3], v[7]);
    ce(v[2], v[4]); ce(v[3], v[5]);
    ce(v[1], v[2]); ce(v[3], v[4]); ce(v[5], v[6]);

    float r = wB[13];
#pragma unroll
    for (int j = 0; j < 8; j++) r = fmaf(v[j], wB[5 + j], r);
    return r;
}

template <int S, int NR>
__device__ __forceinline__ void m_prefetch(float r[NR], const float* __restrict__ src,
                                           int y0, int x0, int tid) {
    constexpr int R = 16 + 2 * S, C = 32 + 2 * S;
#pragma unroll
    for (int j = 0; j < NR; j++) {
        int i = tid + j * 512;
        float v = 0.f;
        if (i < R * C) {
            int rr = i / C, cl = i % C;
            int gy = y0 - S + rr, gx = x0 - S + cl;
            if ((unsigned)gy < 256u && (unsigned)gx < 256u)
                v = __ldg(src + gy * 256 + gx);
        }
        r[j] = v;
    }
}

template <int S, int NR>
__device__ __forceinline__ void m_commit(const float r[NR], float* __restrict__ dst,
                                         int tid) {
    constexpr int R = 16 + 2 * S, C = 32 + 2 * S;
#pragma unroll
    for (int j = 0; j < NR; j++) {
        int i = tid + j * 512;
        if (i < R * C) dst[i] = r[j];
    }
}

__global__ __launch_bounds__(512) void k_main(
    const float* __restrict__ l1_w, const float* __restrict__ l1_b,
    const float* __restrict__ l2_w, const float* __restrict__ l2_b,
    const float* __restrict__ base_w, const float* __restrict__ bn_scale,
    const float* __restrict__ bn_bias, const float* __restrict__ final_w,
    const float* __restrict__ final_b, float* __restrict__ out) {
    // Regions for 32x16 tile: S=1: 18x34=612 @0; S=3: 22x38=836 @612;
    // S=5: 26x42=1092 @1448; S=7: 30x46=1380 @2540; total 3920
    __shared__ float sxt[3920];
    __shared__ float swB[4 * 16 * 14];   // per branch/channel: w1[4],b1,w2[8],b2
    __shared__ float sbase[64];
    __shared__ float sbnS[16], sbnB[16], sfw[16];

    int tid = threadIdx.x;
    for (int i = tid; i < 896; i += 512) {
        int e = i % 14;
        int rest = i / 14;
        int cc = rest % 16, br = rest / 16;
        float v;
        if (e < 4) { v = l1_w[(br * 16 + cc) * 4 + e]; if (e == 3) v *= 2.f; }
        else if (e == 4) v = l1_b[br * 16 + cc];
        else if (e < 13) v = l2_w[(br * 16 + cc) * 8 + (e - 5)];
        else v = l2_b[br * 16 + cc];
        swB[i] = v;
    }
    if (tid < 64) sbase[tid] = base_w[tid];
    if (tid < 16) { sbnS[tid] = bn_scale[tid]; sbnB[tid] = bn_bias[tid]; sfw[tid] = final_w[tid]; }

    int tx = tid & 31, ty = tid >> 5;     // ty 0..15
    int x0 = blockIdx.x * 32, y0 = blockIdx.y * 16;
    int b = blockIdx.z;
    float acc = __ldg(final_b);

    const float* s1 = g_xs + (size_t)((0 * BATCH + b) * 16) * HW;
    const float* s3 = g_xs + (size_t)((1 * BATCH + b) * 16) * HW;
    const float* s5 = g_xs + (size_t)((2 * BATCH + b) * 16) * HW;
    const float* s7 = g_xs + (size_t)((3 * BATCH + b) * 16) * HW;

    float r1[2], r3[2], r5[3], r7[3];
    m_prefetch<1, 2>(r1, s1, y0, x0, tid);
    m_prefetch<3, 2>(r3, s3, y0, x0, tid);
    m_prefetch<5, 3>(r5, s5, y0, x0, tid);
    m_prefetch<7, 3>(r7, s7, y0, x0, tid);

#pragma unroll 1
    for (int c = 0; c < 16; c++) {
        __syncthreads();
        m_commit<1, 2>(r1, sxt + 0,    tid);
        m_commit<3, 2>(r3, sxt + 612,  tid);
        m_commit<5, 3>(r5, sxt + 1448, tid);
        m_commit<7, 3>(r7, sxt + 2540, tid);
        __syncthreads();
        if (c < 15) {
            size_t off = (size_t)(c + 1) * HW;
            m_prefetch<1, 2>(r1, s1 + off, y0, x0, tid);
            m_prefetch<3, 2>(r3, s3 + off, y0, x0, tid);
            m_prefetch<5, 3>(r5, s5 + off, y0, x0, tid);
            m_prefetch<7, 3>(r7, s7 + off, y0, x0, tid);
        }

        float bv0 = branch_val<1, 34>(sxt + 0,    ty, tx, swB + (0 * 16 + c) * 14);
        float bv1 = branch_val<3, 38>(sxt + 612,  ty, tx, swB + (1 * 16 + c) * 14);
        float bv2 = branch_val<5, 42>(sxt + 1448, ty, tx, swB + (2 * 16 + c) * 14);
        float bv3 = branch_val<7, 46>(sxt + 2540, ty, tx, swB + (3 * 16 + c) * 14);

        // sort4 ascending
        ce(bv0, bv1); ce(bv2, bv3); ce(bv0, bv2); ce(bv1, bv3); ce(bv1, bv2);

        float y = bv0 * sbase[c * 4 + 0];
        y = fmaf(bv1, sbase[c * 4 + 1], y);
        y = fmaf(bv2, sbase[c * 4 + 2], y);
        y = fmaf(bv3, sbase[c * 4 + 3], y);
        float t = fmaf(y, sbnS[c], sbnB[c]);
        float si = __fdividef(t, 1.f + __expf(-t));          // SiLU (fast)
        acc = fmaf(si, sfw[c], acc);
    }
    out[(size_t)b * HW + (size_t)(y0 + ty) * 256 + (x0 + tx)] =
        __fdividef(1.f, 1.f + __expf(-acc));
}

// ---------------------------------------------------------------------------
extern "C" void kernel_launch(void* const* d_in, const int* in_sizes, int n_in,
                              void* d_out, int out_size) {
    (void)in_sizes; (void)n_in; (void)out_size;
    const ull* cen = (const ull*)d_in[0];
    // d_in[1] = mas (unused by the reference computation)
    const float* in_w = (const float*)d_in[2];
    const float* in_b = (const float*)d_in[3];

    k_inconv<<<1024, 256>>>(cen, in_w, in_b);

    dim3 g2(8, 16, 8);   // W/32, H/16, B
    k_dw<<<g2, 256>>>((const float*)d_in[4],  (const float*)d_in[5],
                      (const float*)d_in[6],  (const float*)d_in[7],
                      (const float*)d_in[8],  (const float*)d_in[9],
                      (const float*)d_in[10], (const float*)d_in[11]);

    dim3 g3(8, 16, 8);   // W/32, H/16, B
    k_main<<<g3, 512>>>((const float*)d_in[12], (const float*)d_in[13],
                        (const float*)d_in[14], (const float*)d_in[15],
                        (const float*)d_in[16], (const float*)d_in[17],
                        (const float*)d_in[18], (const float*)d_in[19],
                        (const float*)d_in[20], (float*)d_out);
}

// round 8
// speedup vs baseline: 1.1342x; 1.0002x over previous
#include <cuda_runtime.h>

#define HH 256
#define WW 256
#define BATCH 8
#define HW 65536

typedef unsigned long long ull;

// Scratch (allocation-free rule: __device__ globals)
__device__ float g_x[BATCH * 16 * HW];          // in_conv output  (33.5 MB)
__device__ float g_xs[4 * BATCH * 16 * HW];     // dwconv outputs  (134 MB)

// ---------------- packed f32x2 helpers (sm_100+) ----------------
__device__ __forceinline__ ull pk2(float lo, float hi) {
    ull r;
    asm("mov.b64 %0, {%1, %2};" : "=l"(r) : "r"(__float_as_uint(lo)), "r"(__float_as_uint(hi)));
    return r;
}
__device__ __forceinline__ void upk2(ull v, float& lo, float& hi) {
    unsigned a, b;
    asm("mov.b64 {%0, %1}, %2;" : "=r"(a), "=r"(b) : "l"(v));
    lo = __uint_as_float(a); hi = __uint_as_float(b);
}
__device__ __forceinline__ ull fma2(ull a, ull b, ull c) {
    ull d; asm("fma.rn.f32x2 %0, %1, %2, %3;" : "=l"(d) : "l"(a), "l"(b), "l"(c)); return d;
}
__device__ __forceinline__ ull add2(ull a, ull b) {
    ull d; asm("add.rn.f32x2 %0, %1, %2;" : "=l"(d) : "l"(a), "l"(b)); return d;
}
__device__ __forceinline__ ull mul2(ull a, ull b) {
    ull d; asm("mul.rn.f32x2 %0, %1, %2;" : "=l"(d) : "l"(a), "l"(b)); return d;
}

// ---------------------------------------------------------------------------
// K1: 1x1 in_conv 64 -> 16, packed f32x2 FFMA2 (2 px / thread)  [R5, proven]
// ---------------------------------------------------------------------------
__global__ __launch_bounds__(256, 3) void k_inconv(const ull* __restrict__ cen2,
                                                   const float* __restrict__ w,
                                                   const float* __restrict__ bias) {
    __shared__ ull sw[1024];     // {w,w} packed
    __shared__ ull sb[16];
    for (int i = threadIdx.x; i < 1024; i += 256) { float v = w[i]; sw[i] = pk2(v, v); }
    if (threadIdx.x < 16) { float v = bias[threadIdx.x]; sb[threadIdx.x] = pk2(v, v); }
    __syncthreads();

    int idx = blockIdx.x * 256 + threadIdx.x;   // 0 .. 262143  (b, p2)
    int b = idx >> 15;
    int p2 = idx & 32767;
    const ull* cp = cen2 + (size_t)(b * 64) * 32768 + p2;

    ull acc[16];
#pragma unroll
    for (int o = 0; o < 16; o++) acc[o] = sb[o];

#pragma unroll 8
    for (int i = 0; i < 64; i++) {
        ull v = __ldg(cp + (size_t)i * 32768);
#pragma unroll
        for (int o = 0; o < 16; o++) acc[o] = fma2(v, sw[o * 64 + i], acc[o]);
    }
    ull* xp = reinterpret_cast<ull*>(g_x) + (size_t)(b * 16) * 32768 + p2;
#pragma unroll
    for (int o = 0; o < 16; o++) xp[(size_t)o * 32768] = acc[o];
}

// ---------------------------------------------------------------------------
// K2: all 4 depthwise convs (s = 1,3,5,7), tile 32x16, 2 px per thread,
//     register-prefetch pipeline over channels.  [R4, unchanged]
// ---------------------------------------------------------------------------
template <int S>
__device__ __forceinline__ void dw2(const float* __restrict__ sx, int ty, int c0,
                                    const float* __restrict__ wk, float bias,
                                    float& o0, float& o1) {
    constexpr int P = S / 2;
    float a0 = bias, a1 = bias;
#pragma unroll
    for (int kh = 0; kh < S; kh++) {
        const float* row = sx + (ty + 3 - P + kh) * 39 + (c0 + 3 - P);
        float v[S + 1];
#pragma unroll
        for (int j = 0; j <= S; j++) v[j] = row[j];
#pragma unroll
        for (int kw = 0; kw < S; kw++) {
            float wv = wk[kh * S + kw];
            a0 = fmaf(wv, v[kw], a0);
            a1 = fmaf(wv, v[kw + 1], a1);
        }
    }
    o0 = a0; o1 = a1;
}

__device__ __forceinline__ void dw_prefetch(float r[4], const float* __restrict__ src,
                                            int y0, int x0, int tid) {
#pragma unroll
    for (int j = 0; j < 4; j++) {
        int i = tid + j * 256;
        float v = 0.f;
        if (i < 836) {
            int rr = i / 38, cl = i % 38;
            int gy = y0 - 3 + rr, gx = x0 - 3 + cl;
            if ((unsigned)gy < 256u && (unsigned)gx < 256u)
                v = __ldg(src + gy * 256 + gx);
        }
        r[j] = v;
    }
}

__device__ __forceinline__ void dw_commit(const float r[4], float* __restrict__ sxt,
                                          int tid) {
#pragma unroll
    for (int j = 0; j < 4; j++) {
        int i = tid + j * 256;
        if (i < 836) sxt[(i / 38) * 39 + (i % 38)] = r[j];
    }
}

__global__ __launch_bounds__(256) void k_dw(
    const float* __restrict__ w1, const float* __restrict__ b1,
    const float* __restrict__ w3, const float* __restrict__ b3,
    const float* __restrict__ w5, const float* __restrict__ b5,
    const float* __restrict__ w7, const float* __restrict__ b7) {
    __shared__ float sdw[16 * 84];
    __shared__ float sdb[64];
    __shared__ float sxt[22 * 39];

    int tid = threadIdx.x;
    for (int i = tid; i < 16;  i += 256) sdw[i * 84] = w1[i];
    for (int i = tid; i < 144; i += 256) sdw[(i / 9)  * 84 + 1  + (i % 9)]  = w3[i];
    for (int i = tid; i < 400; i += 256) sdw[(i / 25) * 84 + 10 + (i % 25)] = w5[i];
    for (int i = tid; i < 784; i += 256) sdw[(i / 49) * 84 + 35 + (i % 49)] = w7[i];
    if (tid < 16) {
        sdb[tid * 4 + 0] = b1[tid]; sdb[tid * 4 + 1] = b3[tid];
        sdb[tid * 4 + 2] = b5[tid]; sdb[tid * 4 + 3] = b7[tid];
    }

    int ty = tid >> 4;
    int c0 = (tid & 15) * 2;
    int y0 = blockIdx.y * 16, x0 = blockIdx.x * 32;
    int b = blockIdx.z;
    int h = y0 + ty, wc0 = x0 + c0;

    float rb[4];
    dw_prefetch(rb, g_x + (size_t)(b * 16 + 0) * HW, y0, x0, tid);

#pragma unroll 1
    for (int c = 0; c < 16; c++) {
        __syncthreads();
        dw_commit(rb, sxt, tid);
        __syncthreads();
        if (c < 15)
            dw_prefetch(rb, g_x + (size_t)(b * 16 + c + 1) * HW, y0, x0, tid);

        const float* wcp = sdw + c * 84;
        size_t pix = (size_t)h * 256 + wc0;
        float o0, o1;
        dw2<1>(sxt, ty, c0, wcp + 0,  sdb[c * 4 + 0], o0, o1);
        *reinterpret_cast<float2*>(g_xs + (size_t)((0 * BATCH + b) * 16 + c) * HW + pix) = make_float2(o0, o1);
        dw2<3>(sxt, ty, c0, wcp + 1,  sdb[c * 4 + 1], o0, o1);
        *reinterpret_cast<float2*>(g_xs + (size_t)((1 * BATCH + b) * 16 + c) * HW + pix) = make_float2(o0, o1);
        dw2<5>(sxt, ty, c0, wcp + 10, sdb[c * 4 + 2], o0, o1);
        *reinterpret_cast<float2*>(g_xs + (size_t)((2 * BATCH + b) * 16 + c) * HW + pix) = make_float2(o0, o1);
        dw2<7>(sxt, ty, c0, wcp + 35, sdb[c * 4 + 3], o0, o1);
        *reinterpret_cast<float2*>(g_xs + (size_t)((3 * BATCH + b) * 16 + c) * HW + pix) = make_float2(o0, o1);
    }
}

// ---------------------------------------------------------------------------
// K3: fused tail, tile 32x16, 256 threads, 2 px (x-pair) / thread.
// Packed f32x2 math with DUAL-COPY smem so every x-pair tap is one aligned
// LDS.64 (no pack movs): copy E at 8B-aligned base (even pairs), copy O at
// base+4B (odd pairs). Tap parity is compile-time (center odd, dx=+-S even).
// ---------------------------------------------------------------------------
__device__ __forceinline__ void ce(float& a, float& b) {
    float lo = fminf(a, b);
    float hi = fmaxf(a, b);
    a = lo; b = hi;
}

__device__ __forceinline__ void sort8(float v[8]) {
    ce(v[0], v[1]); ce(v[2], v[3]); ce(v[0], v[2]); ce(v[1], v[3]); ce(v[1], v[2]);
    ce(v[4], v[5]); ce(v[6], v[7]); ce(v[4], v[6]); ce(v[5], v[7]); ce(v[5], v[6]);
    ce(v[0], v[4]); ce(v[1], v[5]); ce(v[2], v[6]); ce(v[3], v[7]);
    ce(v[2], v[4]); ce(v[3], v[5]);
    ce(v[1], v[2]); ce(v[3], v[4]); ce(v[5], v[6]);
}

// Region bases (floats), all even: S=1@0(612), S=3@612(836), S=5@1448(1092), S=7@2540(1380)
#define REG_TOTAL 3920

template <int S, int C, int RB>
__device__ __forceinline__ void branch_val2(const float* __restrict__ sE,
                                            const float* __restrict__ sO,
                                            int ty, int tx2,
                                            const ull* __restrict__ wp,
                                            const float* __restrict__ w2,
                                            float& ra, float& rb) {
    const int ctr = RB + (ty + S) * C + 2 * tx2 + S;   // odd (RB, C even; S odd)
    const ull NEG1 = pk2(-1.f, -1.f);
    ull xc = *(const ull*)(sO + ctr);
    ull T[8];
    T[0] = fma2(*(const ull*)(sE + ctr - S * C - S), NEG1, xc);
    T[1] = fma2(*(const ull*)(sO + ctr - S * C),     NEG1, xc);
    T[2] = fma2(*(const ull*)(sE + ctr - S * C + S), NEG1, xc);
    T[3] = fma2(*(const ull*)(sE + ctr + S),         NEG1, xc);
    T[4] = fma2(*(const ull*)(sE + ctr + S * C + S), NEG1, xc);
    T[5] = fma2(*(const ull*)(sO + ctr + S * C),     NEG1, xc);
    T[6] = fma2(*(const ull*)(sE + ctr + S * C - S), NEG1, xc);
    T[7] = fma2(*(const ull*)(sE + ctr - S),         NEG1, xc);

    ull Sv[4];
#pragma unroll
    for (int k = 0; k < 4; k++) Sv[k] = add2(T[k], T[k + 4]);

    ull base[4];
#pragma unroll
    for (int j = 0; j < 4; j++) {
        ull o = fma2(wp[0], Sv[(j + 1) & 3], wp[4]);
        o = fma2(wp[1], Sv[(j + 3) & 3], o);
        base[j] = fma2(wp[2], Sv[(j + 2) & 3], o);
    }
    float va[8], vb[8];
#pragma unroll
    for (int k = 0; k < 8; k++) {
        ull v = mul2(fma2(wp[3], T[(k + 4) & 7], base[k & 3]), T[k]);
        upk2(v, va[k], vb[k]);
    }
    sort8(va);
    sort8(vb);
    float aa = w2[8], bb = w2[8];
#pragma unroll
    for (int j = 0; j < 8; j++) {
        float wv = w2[j];
        aa = fmaf(va[j], wv, aa);
        bb = fmaf(vb[j], wv, bb);
    }
    ra = aa; rb = bb;
}

template <int S, int NR>
__device__ __forceinline__ void m_prefetch(float r[NR], const float* __restrict__ src,
                                           int y0, int x0, int tid) {
    constexpr int R = 16 + 2 * S, C = 32 + 2 * S;
#pragma unroll
    for (int j = 0; j < NR; j++) {
        int i = tid + j * 256;
        float v = 0.f;
        if (i < R * C) {
            int rr = i / C, cl = i % C;
            int gy = y0 - S + rr, gx = x0 - S + cl;
            if ((unsigned)gy < 256u && (unsigned)gx < 256u)
                v = __ldg(src + gy * 256 + gx);
        }
        r[j] = v;
    }
}

template <int S, int NR>
__device__ __forceinline__ void m_commit2(const float r[NR], float* __restrict__ dE,
                                          float* __restrict__ dO, int tid) {
    constexpr int R = 16 + 2 * S, C = 32 + 2 * S;
#pragma unroll
    for (int j = 0; j < NR; j++) {
        int i = tid + j * 256;
        if (i < R * C) { dE[i] = r[j]; dO[i] = r[j]; }
    }
}

__global__ __launch_bounds__(256) void k_main(
    const float* __restrict__ l1_w, const float* __restrict__ l1_b,
    const float* __restrict__ l2_w, const float* __restrict__ l2_b,
    const float* __restrict__ base_w, const float* __restrict__ bn_scale,
    const float* __restrict__ bn_bias, const float* __restrict__ final_w,
    const float* __restrict__ final_b, float* __restrict__ out) {
    __shared__ ull sE8[REG_TOTAL / 2];        // even-pair copy (8B aligned)
    __shared__ ull sO8[REG_TOTAL / 2 + 1];    // odd-pair copy at +4B
    __shared__ ull swp[320];                  // packed l1 wts [br][c][5]: w10,w11,w12,2w13,b1
    __shared__ float sw2[576];                // l2 wts+bias [br][c][9]
    __shared__ float sbase[64];
    __shared__ float sbnS[16], sbnB[16], sfw[16];

    float* sE = reinterpret_cast<float*>(sE8);
    float* sO = reinterpret_cast<float*>(sO8) + 1;

    int tid = threadIdx.x;
    for (int i = tid; i < 320; i += 256) {
        int br = i / 80, c = (i / 5) & 15, e = i % 5;
        float v = (e < 4) ? l1_w[(br * 16 + c) * 4 + e] : l1_b[br * 16 + c];
        if (e == 3) v *= 2.f;
        swp[i] = pk2(v, v);
    }
    for (int i = tid; i < 576; i += 256) {
        int br = i / 144, c = (i / 9) & 15, e = i % 9;
        sw2[i] = (e < 8) ? l2_w[(br * 16 + c) * 8 + e] : l2_b[br * 16 + c];
    }
    if (tid < 64) sbase[tid] = base_w[tid];
    if (tid < 16) { sbnS[tid] = bn_scale[tid]; sbnB[tid] = bn_bias[tid]; sfw[tid] = final_w[tid]; }

    int tx2 = tid & 15, ty = tid >> 4;        // x-pair 0..15, row 0..15
    int x0 = blockIdx.x * 32, y0 = blockIdx.y * 16;
    int b = blockIdx.z;
    float fb = __ldg(final_b);
    float acc0 = fb, acc1 = fb;

    const float* s1 = g_xs + (size_t)((0 * BATCH + b) * 16) * HW;
    const float* s3 = g_xs + (size_t)((1 * BATCH + b) * 16) * HW;
    const float* s5 = g_xs + (size_t)((2 * BATCH + b) * 16) * HW;
    const float* s7 = g_xs + (size_t)((3 * BATCH + b) * 16) * HW;

    float r1[3], r3[4], r5[5], r7[6];
    m_prefetch<1, 3>(r1, s1, y0, x0, tid);
    m_prefetch<3, 4>(r3, s3, y0, x0, tid);
    m_prefetch<5, 5>(r5, s5, y0, x0, tid);
    m_prefetch<7, 6>(r7, s7, y0, x0, tid);

#pragma unroll 1
    for (int c = 0; c < 16; c++) {
        __syncthreads();
        m_commit2<1, 3>(r1, sE + 0,    sO + 0,    tid);
        m_commit2<3, 4>(r3, sE + 612,  sO + 612,  tid);
        m_commit2<5, 5>(r5, sE + 1448, sO + 1448, tid);
        m_commit2<7, 6>(r7, sE + 2540, sO + 2540, tid);
        __syncthreads();
        if (c < 15) {
            size_t off = (size_t)(c + 1) * HW;
            m_prefetch<1, 3>(r1, s1 + off, y0, x0, tid);
            m_prefetch<3, 4>(r3, s3 + off, y0, x0, tid);
            m_prefetch<5, 5>(r5, s5 + off, y0, x0, tid);
            m_prefetch<7, 6>(r7, s7 + off, y0, x0, tid);
        }

        float bva[4], bvb[4];
        branch_val2<1, 34, 0>   (sE, sO, ty, tx2, swp + (0 * 16 + c) * 5, sw2 + (0 * 16 + c) * 9, bva[0], bvb[0]);
        branch_val2<3, 38, 612> (sE, sO, ty, tx2, swp + (1 * 16 + c) * 5, sw2 + (1 * 16 + c) * 9, bva[1], bvb[1]);
        branch_val2<5, 42, 1448>(sE, sO, ty, tx2, swp + (2 * 16 + c) * 5, sw2 + (2 * 16 + c) * 9, bva[2], bvb[2]);
        branch_val2<7, 46, 2540>(sE, sO, ty, tx2, swp + (3 * 16 + c) * 5, sw2 + (3 * 16 + c) * 9, bva[3], bvb[3]);

        // sort4 ascending per px
        ce(bva[0], bva[1]); ce(bva[2], bva[3]); ce(bva[0], bva[2]); ce(bva[1], bva[3]); ce(bva[1], bva[2]);
        ce(bvb[0], bvb[1]); ce(bvb[2], bvb[3]); ce(bvb[0], bvb[2]); ce(bvb[1], bvb[3]); ce(bvb[1], bvb[2]);

        float y0v = bva[0] * sbase[c * 4 + 0];
        y0v = fmaf(bva[1], sbase[c * 4 + 1], y0v);
        y0v = fmaf(bva[2], sbase[c * 4 + 2], y0v);
        y0v = fmaf(bva[3], sbase[c * 4 + 3], y0v);
        float y1v = bvb[0] * sbase[c * 4 + 0];
        y1v = fmaf(bvb[1], sbase[c * 4 + 1], y1v);
        y1v = fmaf(bvb[2], sbase[c * 4 + 2], y1v);
        y1v = fmaf(bvb[3], sbase[c * 4 + 3], y1v);
        float t0 = fmaf(y0v, sbnS[c], sbnB[c]);
        float t1 = fmaf(y1v, sbnS[c], sbnB[c]);
        float si0 = __fdividef(t0, 1.f + __expf(-t0));
        float si1 = __fdividef(t1, 1.f + __expf(-t1));
        acc0 = fmaf(si0, sfw[c], acc0);
        acc1 = fmaf(si1, sfw[c], acc1);
    }
    float2 o = make_float2(__fdividef(1.f, 1.f + __expf(-acc0)),
                           __fdividef(1.f, 1.f + __expf(-acc1)));
    *reinterpret_cast<float2*>(out + (size_t)b * HW + (size_t)(y0 + ty) * 256 +
                               (x0 + 2 * tx2)) = o;
}

// ---------------------------------------------------------------------------
extern "C" void kernel_launch(void* const* d_in, const int* in_sizes, int n_in,
                              void* d_out, int out_size) {
    (void)in_sizes; (void)n_in; (void)out_size;
    const ull* cen = (const ull*)d_in[0];
    // d_in[1] = mas (unused by the reference computation)
    const float* in_w = (const float*)d_in[2];
    const float* in_b = (const float*)d_in[3];

    k_inconv<<<1024, 256>>>(cen, in_w, in_b);

    dim3 g2(8, 16, 8);   // W/32, H/16, B
    k_dw<<<g2, 256>>>((const float*)d_in[4],  (const float*)d_in[5],
                      (const float*)d_in[6],  (const float*)d_in[7],
                      (const float*)d_in[8],  (const float*)d_in[9],
                      (const float*)d_in[10], (const float*)d_in[11]);

    dim3 g3(8, 16, 8);   // W/32, H/16, B
    k_main<<<g3, 256>>>((const float*)d_in[12], (const float*)d_in[13],
                        (const float*)d_in[14], (const float*)d_in[15],
                        (const float*)d_in[16], (const float*)d_in[17],
                        (const float*)d_in[18], (const float*)d_in[19],
                        (const float*)d_in[20], (float*)d_out);
}